// round 7
// baseline (speedup 1.0000x reference)
#include <cuda_runtime.h>

// RayTracing, two-phase, two launches:
//  A) per-ray sphere tracing -> writes all outputs, compacts unfinished (smask)
//     ray ids into a device queue (warp-aggregated atomics).
//  B) sampler over the compacted queue, 4 LANES PER RAY: each lane scans a
//     contiguous 25-step block (sqrt-free: sign via |p|^2 < 0.25, argmin of
//     |p|^2), quad-reduced via shuffles with exact first-occurrence tie-break.
//     Secant computed redundantly by all 4 lanes; lane 0 writes.
//     Last-finishing block resets the queue counter for the next replay.
//
// Output layout (float32): [curr_pts (N*3)][net_mask (N)][acc_s (N)], N = out_size/5.
// object_mask arrives as int32.

namespace rt {

constexpr int   MAXN       = 262144;
constexpr int   ST_ITERS   = 10;
constexpr float SDF_THRESH = 5e-5f;
constexpr int   NSTEPS     = 100;
constexpr int   NSECANT    = 8;
constexpr float INV99      = 1.0f / 99.0f;
constexpr float R2THRESH   = 0.25f;   // SDF_RADIUS^2
constexpr int   LPR        = 4;       // lanes per ray
constexpr int   KPL        = NSTEPS / LPR;  // 25 steps per lane

__device__ int   g_count;   // zero-init at module load; sampler re-zeroes per run
__device__ int   g_done;
__device__ int   g_queue[MAXN];
__device__ float g_smin[MAXN];
__device__ float g_smax[MAXN];

__device__ __forceinline__ float fsqrt_fast(float x) {
    float y;
    asm("sqrt.approx.f32 %0, %1;" : "=f"(y) : "f"(x));
    return y;
}

// sdf(p) = sqrt(|p|^2 + 1e-12) - 0.5
__device__ __forceinline__ float sdf_p(float px, float py, float pz) {
    float q = fmaf(px, px, fmaf(py, py, fmaf(pz, pz, 1e-12f)));
    return fsqrt_fast(q) - 0.5f;
}

__device__ __forceinline__ float sdf_at(float ox, float oy, float oz,
                                        float dx, float dy, float dz, float t) {
    return sdf_p(fmaf(t, dx, ox), fmaf(t, dy, oy), fmaf(t, dz, oz));
}

// |o + t*d|^2 + 1e-12 (no sqrt)
__device__ __forceinline__ float q_at(float ox, float oy, float oz,
                                      float dx, float dy, float dz, float t) {
    float px = fmaf(t, dx, ox);
    float py = fmaf(t, dy, oy);
    float pz = fmaf(t, dz, oz);
    return fmaf(px, px, fmaf(py, py, fmaf(pz, pz, 1e-12f)));
}

// ---------------- Phase A: trace + compact ----------------
__global__ void __launch_bounds__(256)
trace_kernel(const float* __restrict__ cam,
             const float* __restrict__ dirs,
             float* __restrict__ out, int n)
{
    int i = blockIdx.x * blockDim.x + threadIdx.x;
    bool valid = i < n;
    int j = valid ? i : 0;

    float ox = cam[3 * j + 0], oy = cam[3 * j + 1], oz = cam[3 * j + 2];
    float dx = dirs[3 * j + 0], dy = dirs[3 * j + 1], dz = dirs[3 * j + 2];

    // ---- sphere intersect with bounding sphere R=1 ----
    float a = fmaf(dx, dx, fmaf(dy, dy, dz * dz));
    float b = 2.0f * fmaf(ox, dx, fmaf(oy, dy, oz * dz));
    float c = fmaf(ox, ox, fmaf(oy, oy, oz * oz)) - 1.0f;
    float under = fmaf(b, b, -4.0f * a * c);
    bool  mask = under > 0.0f;
    float sq = fsqrt_fast(fmaxf(under, 0.0f));
    float nearv = mask ? (-sq - b) * 0.5f : 0.0f;
    float farv  = mask ? ( sq - b) * 0.5f : 0.0f;
    nearv = fmaxf(nearv, 0.01f);
    farv  = fmaxf(farv, 0.01f);

    // ---- sphere tracing (bidirectional) ----
    bool us = mask, ue = mask;
    float accs = nearv, acce = farv;
    float csx = mask ? fmaf(nearv, dx, ox) : 0.0f;
    float csy = mask ? fmaf(nearv, dy, oy) : 0.0f;
    float csz = mask ? fmaf(nearv, dz, oz) : 0.0f;
    float cex = mask ? fmaf(farv, dx, ox) : 0.0f;
    float cey = mask ? fmaf(farv, dy, oy) : 0.0f;
    float cez = mask ? fmaf(farv, dz, oz) : 0.0f;
    float ns = us ? sdf_p(csx, csy, csz) : 0.0f;
    float ne = ue ? sdf_p(cex, cey, cez) : 0.0f;

#pragma unroll
    for (int it = 0; it < ST_ITERS; ++it) {
        float cs = us ? ns : 0.0f;
        cs = (cs <= SDF_THRESH) ? 0.0f : cs;
        us = us && (cs > SDF_THRESH);
        float ce = ue ? ne : 0.0f;
        ce = (ce <= SDF_THRESH) ? 0.0f : ce;
        ue = ue && (ce > SDF_THRESH);

        accs += cs;
        acce -= ce;
        csx = fmaf(accs, dx, ox); csy = fmaf(accs, dy, oy); csz = fmaf(accs, dz, oz);
        cex = fmaf(acce, dx, ox); cey = fmaf(acce, dy, oy); cez = fmaf(acce, dz, oz);
        ns = us ? sdf_p(csx, csy, csz) : 0.0f;
        ne = ue ? sdf_p(cex, cey, cez) : 0.0f;

        // line search: LINE_STEP_ITERS = 1, step = 0.5
        bool nps = ns < 0.0f;
        bool npe = ne < 0.0f;
        {
            float accs2 = fmaf(-0.5f, cs, accs);
            float x = fmaf(accs2, dx, ox), y = fmaf(accs2, dy, oy), z = fmaf(accs2, dz, oz);
            float s2 = sdf_p(x, y, z);
            if (nps) { accs = accs2; csx = x; csy = y; csz = z; ns = s2; }
        }
        {
            float acce2 = fmaf(0.5f, ce, acce);
            float x = fmaf(acce2, dx, ox), y = fmaf(acce2, dy, oy), z = fmaf(acce2, dz, oz);
            float s2 = sdf_p(x, y, z);
            if (npe) { acce = acce2; cex = x; cey = y; cez = z; ne = s2; }
        }
        bool ok = accs < acce;
        us = us && ok;
        ue = ue && ok;
    }
    // final _upd_mask on start side
    {
        float cs = us ? ns : 0.0f;
        cs = (cs <= SDF_THRESH) ? 0.0f : cs;
        us = us && (cs > SDF_THRESH);
    }

    bool netm  = accs < acce;
    bool smask = us && valid;

    if (valid) {
        out[3 * i + 0] = csx;
        out[3 * i + 1] = csy;
        out[3 * i + 2] = csz;
        out[3 * n + i] = netm ? 1.0f : 0.0f;
        out[4 * n + i] = accs;
    }

    // warp-aggregated queue push of smask rays
    unsigned bal = __ballot_sync(0xffffffffu, smask);
    if (smask) {
        int lane = threadIdx.x & 31;
        int leader = __ffs(bal) - 1;
        unsigned pos = 0;
        if (lane == leader) pos = atomicAdd(&g_count, __popc(bal));
        pos = __shfl_sync(bal, pos, leader);
        int myoff = __popc(bal & ((1u << lane) - 1));
        int q = (int)pos + myoff;
        g_queue[q] = i;
        g_smin[q] = accs;
        g_smax[q] = acce;
    }
}

// ---------------- Phase B: sampler + secant, 4 lanes per ray ----------------
__global__ void __launch_bounds__(256)
sampler_kernel(const float* __restrict__ cam,
               const float* __restrict__ dirs,
               const int* __restrict__ objm,
               float* __restrict__ out, int n)
{
    const unsigned FULL = 0xffffffffu;
    int cnt = g_count;   // read BEFORE any work (reset protocol relies on this)

    int lane = threadIdx.x & 31;
    int sub  = lane & (LPR - 1);          // lane within quad: 0..3
    int quad_in_warp = lane >> 2;          // 0..7
    int warp_global = (blockIdx.x * blockDim.x + threadIdx.x) >> 5;
    int quads_total = (gridDim.x * blockDim.x) >> 2;

    for (int q0 = warp_global * 8 + quad_in_warp; ; q0 += quads_total) {
        bool active = q0 < cnt;
        if (!__any_sync(FULL, active)) break;
        int q = active ? q0 : 0;          // clamped dummy work for inactive quads

        int rid = g_queue[q];
        float smin = g_smin[q];
        float smax = g_smax[q];
        float range = smax - smin;

        float ox = cam[3 * rid + 0], oy = cam[3 * rid + 1], oz = cam[3 * rid + 2];
        float dx = dirs[3 * rid + 0], dy = dirs[3 * rid + 1], dz = dirs[3 * rid + 2];
        bool obj = objm[rid] != 0;

        // lane-local scan over k in [sub*25, sub*25+25), exact per-k math
        int   kbase = sub * KPL;
        int   ind_neg = NSTEPS, oidx = NSTEPS - 1;
        float best_q = 1e30f;
#pragma unroll 5
        for (int kk = 0; kk < KPL; ++kk) {
            int   k  = kbase + kk;
            float t  = (float)k * INV99;
            float z  = fmaf(t, range, smin);
            float qv = q_at(ox, oy, oz, dx, dy, dz, z);
            ind_neg  = min(ind_neg, (qv < R2THRESH) ? k : NSTEPS);
            if (qv < best_q) { best_q = qv; oidx = k; }
        }

        // quad reduction (xor 1, 2 stays within the quad)
#pragma unroll
        for (int m = 1; m < LPR; m <<= 1) {
            int   in2 = __shfl_xor_sync(FULL, ind_neg, m);
            float bq2 = __shfl_xor_sync(FULL, best_q, m);
            int   oi2 = __shfl_xor_sync(FULL, oidx, m);
            ind_neg = min(ind_neg, in2);
            // first-occurrence argmin: smaller q wins, tie -> smaller index
            if (bq2 < best_q || (bq2 == best_q && oi2 < oidx)) {
                best_q = bq2; oidx = oi2;
            }
        }
        int ind = (ind_neg < NSTEPS) ? ind_neg : (NSTEPS - 1);

        // exact values at tracked indices (all lanes redundantly)
        float z_ind = fmaf((float)ind * INV99, range, smin);
        float s_ind = sdf_at(ox, oy, oz, dx, dy, dz, z_ind);
        bool  net_surface = s_ind < 0.0f;
        bool  p_out = !(obj && net_surface);
        float z_o = fmaf((float)oidx * INV99, range, smin);

        int   ilow = (ind > 0) ? (ind - 1) : 0;
        float z_l  = fmaf((float)ilow * INV99, range, smin);
        float s_l  = sdf_at(ox, oy, oz, dx, dy, dz, z_l);

        // ---- secant refinement ----
        float sl = s_l, sh = s_ind, zl = z_l, zh = z_ind;
        float den = sh - sl;
        den = (den == 0.0f) ? 1.0f : den;
        float z = zl - sl * (zh - zl) / den;
#pragma unroll
        for (int k = 0; k < NSECANT; ++k) {
            float s = sdf_at(ox, oy, oz, dx, dy, dz, z);
            if (s > 0.0f) { zl = z; sl = s; }
            if (s < 0.0f) { zh = z; sh = s; }
            den = sh - sl;
            den = (den == 0.0f) ? 1.0f : den;
            z = zl - sl * (zh - zl) / den;
        }

        // ---- select outputs ----
        float zsel = z_ind;
        if (p_out) zsel = z_o;
        bool sec = net_surface && obj;
        if (sec) zsel = z;
        bool snet = net_surface;

        if (active && sub == 0) {
            out[3 * rid + 0] = fmaf(zsel, dx, ox);
            out[3 * rid + 1] = fmaf(zsel, dy, oy);
            out[3 * rid + 2] = fmaf(zsel, dz, oz);
            out[3 * n + rid] = snet ? 1.0f : 0.0f;
            out[4 * n + rid] = zsel;
        }
    }

    // Last-finishing block resets the queue counter for the next replay.
    __syncthreads();
    if (threadIdx.x == 0) {
        __threadfence();
        int done = atomicAdd(&g_done, 1);
        if (done == gridDim.x - 1) {
            g_count = 0;
            g_done  = 0;
            __threadfence();
        }
    }
}

} // namespace rt

extern "C" void kernel_launch(void* const* d_in, const int* in_sizes, int n_in,
                              void* d_out, int out_size)
{
    const float* cam  = (const float*)d_in[0];
    const float* dirs = (const float*)d_in[1];
    const int*   objm = (const int*)d_in[2];
    float* out = (float*)d_out;

    int n = out_size / 5;
    int threads = 256;
    int blocks = (n + threads - 1) / threads;

    rt::trace_kernel<<<blocks, threads>>>(cam, dirs, out, n);
    rt::sampler_kernel<<<1184, threads>>>(cam, dirs, objm, out, n);
}